// round 12
// baseline (speedup 1.0000x reference)
#include <cuda_runtime.h>
#include <cuda_bf16.h>
#include <math.h>
#include <stdint.h>

#define TSTEPS  20
#define NLAYERS 4
#define DM      512
#define DS      128
#define ROWS    2048      // BATCH(4) * SEQ(512)
#define VOCAB   32000

// ---------------- scratch (device globals; no allocations allowed) ----------
__device__ uint32_t      g_bits[2][TSTEPS][ROWS][16];
__device__ float         g_AT[NLAYERS][DS * DS];      // AT[j*DS+i] = A[i][j]
__device__ float         g_BT[NLAYERS][DM * DS];      // BT[d*DS+i] = B[i][d]
__device__ float         g_CT[NLAYERS][DS * DM];      // CT[i*DM+d] = C[d][i]
__device__ __nv_bfloat16 g_cntb[ROWS * DM];           // exact integer spike counts
__device__ __nv_bfloat16 g_wph[(size_t)VOCAB * DM];   // bf16 hi of Wp
__device__ __nv_bfloat16 g_wpl[(size_t)VOCAB * DM];   // bf16 lo of Wp

// ---------------- weight transposes ----------------------------------------
__global__ void prep_kernel(const float* __restrict__ A,
                            const float* __restrict__ Bm,
                            const float* __restrict__ Cm) {
    int stride = gridDim.x * blockDim.x;
    int gid = blockIdx.x * blockDim.x + threadIdx.x;
    for (int idx = gid; idx < NLAYERS * DS * DS; idx += stride) {
        int l = idx / (DS * DS); int rm = idx % (DS * DS);
        int i = rm / DS, j = rm % DS;
        g_AT[l][j * DS + i] = A[idx];
    }
    for (int idx = gid; idx < NLAYERS * DS * DM; idx += stride) {
        int l = idx / (DS * DM); int rm = idx % (DS * DM);
        int i = rm / DM, d = rm % DM;
        g_BT[l][d * DS + i] = Bm[idx];
    }
    for (int idx = gid; idx < NLAYERS * DM * DS; idx += stride) {
        int l = idx / (DM * DS); int rm = idx % (DM * DS);
        int d = rm / DS, i = rm % DS;
        g_CT[l][i * DM + d] = Cm[idx];
    }
}

// ---------------- Wp two-term bf16 split ------------------------------------
__global__ void split_wp_kernel(const float* __restrict__ Wp) {
    long long i = (long long)blockIdx.x * blockDim.x + threadIdx.x;
    if (i >= (long long)VOCAB * DM) return;
    float w = Wp[i];
    __nv_bfloat16 h = __float2bfloat16(w);
    g_wph[i] = h;
    g_wpl[i] = __float2bfloat16(w - __bfloat162float(h));
}

__global__ void zero_bits_kernel() {
    int gid = blockIdx.x * blockDim.x + threadIdx.x;
    uint32_t* p = &g_bits[0][0][0][0];
    int n = TSTEPS * ROWS * 16;          // buffer 0 (encode's atomicOr target)
    for (int i = gid; i < n; i += gridDim.x * blockDim.x) p[i] = 0u;
}

// ---------------- temporal encoding (exact fp32 logistic, as validated) -----
__global__ void encode_kernel(const int* __restrict__ ids,
                              const float* __restrict__ emb) {
    int gid = blockIdx.x * blockDim.x + threadIdx.x;
    if (gid >= ROWS * DM) return;
    int r = gid >> 9, d = gid & (DM - 1);
    float x = emb[(long long)ids[r] * DM + d];
    float sgf = 1.0f / (1.0f + expf(-x));
    int t = (int)floorf(sgf * 19.0f);
    if (t < 0) t = 0;
    if (t > 19) t = 19;
    atomicOr(&g_bits[0][t][r][d >> 5], 1u << (d & 31));
}

// ---------------- one LIF-SSM layer (bit-exact arithmetic, fewer stalls) ----
// 1 row per 128-thread CTA. Same ascending-order sparse sums and separately
// rounded dots as the validated kernel. Changes are stall-removal only:
//   * 4 __syncthreads per timestep (was 6):
//       S_a: prior iteration's sh_x/sh_xidx consumers done -> safe to rewrite
//       S_b: x words + index list visible to all warps
//       S2 : all warps past A-gather (old sh_hidx) and sh_h writes visible
//       S3 : new sh_hidx/sh_nh visible before C-gather
//     sh_h write moved BEFORE S2: its only reader (warp0 unpack) runs in the
//     S2->S3 window; previous-timestep unpack finished before S3(prev)<S_a.
//   * g_bits[t+1] prefetched right after S_b so the ~400cyc LDG overlaps the
//     gather phase instead of serializing warp0 against the barrier.
// last!=0: counts accumulate in registers; writes g_cntb, not g_bits.
__global__ __launch_bounds__(128) void ssm_kernel(int layer, int inb, int outb,
                                                  const float* __restrict__ Dfull,
                                                  int last) {
    int r   = blockIdx.x;
    int tid = threadIdx.x;
    int lane = tid & 31, wp = tid >> 5;
    const float* __restrict__ AT = g_AT[layer];
    const float* __restrict__ BT = g_BT[layer];
    const float* __restrict__ CT = g_CT[layer];
    const float* __restrict__ Dv = Dfull + layer * DM;

    __shared__ uint32_t sh_x[16];
    __shared__ uint32_t sh_h[4];
    __shared__ int sh_xidx[512];
    __shared__ int sh_hidx[128];
    __shared__ int sh_nx, sh_nh;

    float v1 = 0.f;
    float v2[4] = {0.f, 0.f, 0.f, 0.f};
    float cnt[4] = {0.f, 0.f, 0.f, 0.f};
    if (tid == 0) sh_nh = 0;

    uint32_t wpre = 0;
    if (tid < 16) wpre = g_bits[inb][0][r][tid];

    for (int t = 0; t < TSTEPS; t++) {
        __syncthreads();                       // S_a
        if (tid < 16) {
            uint32_t w = wpre;
            sh_x[tid] = w;
            int c = __popc(w);
            int incl = c;
            #pragma unroll
            for (int off = 1; off < 16; off <<= 1) {
                int y = __shfl_up_sync(0xffffu, incl, off);
                if (tid >= off) incl += y;
            }
            int pos = incl - c;
            while (w) {
                int b = __ffs(w) - 1; w &= w - 1;
                sh_xidx[pos++] = ((tid << 5) + b) * DS;
            }
            if (tid == 15) sh_nx = incl;
        }
        __syncthreads();                       // S_b

        if (tid < 16 && t + 1 < TSTEPS)        // prefetch next timestep's words
            wpre = g_bits[inb][t + 1][r][tid];

        int nh = sh_nh, nx = sh_nx;
        float sa = 0.f;
        #pragma unroll 4
        for (int i = 0; i < nh; i++) sa += AT[sh_hidx[i] * DS + tid];
        float sb = 0.f;
        #pragma unroll 8
        for (int i = 0; i < nx; i++) sb += BT[sh_xidx[i] + tid];
        float u = sa + sb;

        v1 = v1 + (u - v1) * 0.5f;
        int s1 = (v1 - 1.0f) >= 0.f;
        uint32_t hb = __ballot_sync(0xffffffffu, s1);
        if (s1) v1 = 0.f;
        if (lane == 0) sh_h[wp] = hb;
        __syncthreads();                       // S2

        if (tid < 4) {
            uint32_t w = sh_h[tid];
            int c = __popc(w);
            int incl = c;
            #pragma unroll
            for (int off = 1; off < 4; off <<= 1) {
                int y = __shfl_up_sync(0xfu, incl, off);
                if (tid >= off) incl += y;
            }
            int pos = incl - c;
            while (w) {
                int b = __ffs(w) - 1; w &= w - 1;
                sh_hidx[pos++] = (tid << 5) + b;
            }
            if (tid == 3) sh_nh = incl;
        }
        __syncthreads();                       // S3

        int nh2 = sh_nh;
        float sc0 = 0.f, sc1 = 0.f, sc2 = 0.f, sc3 = 0.f;
        #pragma unroll 2
        for (int i = 0; i < nh2; i++) {
            const float* crow = CT + sh_hidx[i] * DM + tid;
            sc0 += crow[0];
            sc1 += crow[128];
            sc2 += crow[256];
            sc3 += crow[384];
        }
        float sc[4] = {sc0, sc1, sc2, sc3};
        #pragma unroll
        for (int k = 0; k < 4; k++) {
            float u2 = sc[k];
            if ((sh_x[4 * k + wp] >> lane) & 1u) u2 = u2 + Dv[tid + 128 * k];
            v2[k] = v2[k] + (u2 - v2[k]) * 0.5f;
            int s2 = (v2[k] - 1.0f) >= 0.f;
            if (!last) {
                uint32_t ob = __ballot_sync(0xffffffffu, s2);
                if (lane == 0) g_bits[outb][t][r][4 * k + wp] = ob;
            } else {
                cnt[k] += s2 ? 1.0f : 0.0f;
            }
            if (s2) v2[k] = 0.f;
        }
    }

    if (last) {
        #pragma unroll
        for (int k = 0; k < 4; k++)
            g_cntb[(size_t)r * DM + tid + 128 * k] = __float2bfloat16(cnt[k]);
    }
}

// ============ logits GEMM: split-bf16 mma.sync + ldmatrix, 3-stage cp.async ==
#define SPAD   40                        // bf16 per smem row (80 B pitch)
#define KC     32                        // K per chunk
#define NCH    (DM / KC)                 // 16 chunks
#define ST     3                         // pipeline stages
#define MAT_B  (128 * SPAD * 2)          // 10240 B per matrix tile
#define STAGE_B (3 * MAT_B)              // A + Bh + Bl
#define GSMEM_BYTES (ST * STAGE_B)       // 92160

__device__ __forceinline__ void mma16816(float* d, const uint32_t* a, const uint32_t* b) {
    asm volatile(
        "mma.sync.aligned.m16n8k16.row.col.f32.bf16.bf16.f32 "
        "{%0,%1,%2,%3}, {%4,%5,%6,%7}, {%8,%9}, {%0,%1,%2,%3};"
        : "+f"(d[0]), "+f"(d[1]), "+f"(d[2]), "+f"(d[3])
        : "r"(a[0]), "r"(a[1]), "r"(a[2]), "r"(a[3]), "r"(b[0]), "r"(b[1]));
}
__device__ __forceinline__ void ldmx4(uint32_t* r, uint32_t a) {
    asm volatile("ldmatrix.sync.aligned.m8n8.x4.shared.b16 {%0,%1,%2,%3}, [%4];"
        : "=r"(r[0]), "=r"(r[1]), "=r"(r[2]), "=r"(r[3]) : "r"(a));
}
__device__ __forceinline__ void ldmx2(uint32_t* r, uint32_t a) {
    asm volatile("ldmatrix.sync.aligned.m8n8.x2.shared.b16 {%0,%1}, [%2];"
        : "=r"(r[0]), "=r"(r[1]) : "r"(a));
}
__device__ __forceinline__ void cpasync16(uint32_t dst, const void* src) {
    asm volatile("cp.async.ca.shared.global [%0], [%1], 16;" :: "r"(dst), "l"(src));
}
__device__ __forceinline__ uint32_t smem_u32(const void* p) {
    uint32_t a;
    asm("{ .reg .u64 t; cvta.to.shared.u64 t, %1; cvt.u32.u64 %0, t; }"
        : "=r"(a) : "l"(p));
    return a;
}

__global__ __launch_bounds__(256, 2) void gemm_bf16_kernel(const float* __restrict__ bp,
                                                           float* __restrict__ out) {
    extern __shared__ char smem[];
    uint32_t sbase = smem_u32(smem);

    int bm = blockIdx.x, bn = blockIdx.y;   // bm fastest -> Wp tile reused in L2
    int tid = threadIdx.x;
    int w   = tid >> 5;
    int wm  = w >> 2, wn = w & 3;           // 2 x 4 warps
    int lane = tid & 31;
    int g = lane >> 2, tig = lane & 3;

    const __nv_bfloat16* asrc = g_cntb + (size_t)(bm * 128) * DM;
    const __nv_bfloat16* hsrc = g_wph  + (size_t)(bn * 128) * DM;
    const __nv_bfloat16* lsrc = g_wpl  + (size_t)(bn * 128) * DM;

    int a_q = lane >> 3, a_r = lane & 7;
    uint32_t a_off = (uint32_t)(((wm * 64 + (a_q & 1) * 8 + a_r) * SPAD +
                                 (a_q >> 1) * 8) * 2);
    int b_r = lane & 7, b_q = (lane >> 3) & 1;
    uint32_t b_off = (uint32_t)(((wn * 32 + b_r) * SPAD + b_q * 8) * 2);

    int crow  = tid >> 1;
    int chalf = (tid & 1) * 32;

    auto issue_stage = [&](int s, int c) {
        uint32_t dbase = sbase + s * STAGE_B + crow * (SPAD * 2) + chalf;
        size_t goff = (size_t)crow * DM + c * KC + (chalf >> 1);
        cpasync16(dbase,                  asrc + goff);
        cpasync16(dbase + 16,             asrc + goff + 8);
        cpasync16(dbase + MAT_B,          hsrc + goff);
        cpasync16(dbase + MAT_B + 16,     hsrc + goff + 8);
        cpasync16(dbase + 2 * MAT_B,      lsrc + goff);
        cpasync16(dbase + 2 * MAT_B + 16, lsrc + goff + 8);
    };

    #pragma unroll
    for (int s = 0; s < ST - 1; s++) {
        issue_stage(s, s);
        asm volatile("cp.async.commit_group;" ::: "memory");
    }

    float acc[4][4][4];
    #pragma unroll
    for (int i = 0; i < 4; i++)
        #pragma unroll
        for (int j = 0; j < 4; j++)
            #pragma unroll
            for (int q = 0; q < 4; q++) acc[i][j][q] = 0.f;

    #pragma unroll 1
    for (int c = 0; c < NCH; c++) {
        if (c < NCH - 1) asm volatile("cp.async.wait_group 1;" ::: "memory");
        else             asm volatile("cp.async.wait_group 0;" ::: "memory");
        __syncthreads();

        if (c + 2 < NCH) {
            issue_stage((c + 2) % ST, c + 2);
            asm volatile("cp.async.commit_group;" ::: "memory");
        }

        uint32_t st = sbase + (c % ST) * STAGE_B;

        #pragma unroll
        for (int ks = 0; ks < KC / 16; ks++) {
            uint32_t kof = (uint32_t)(ks * 16 * 2);
            uint32_t afr[4][4];
            #pragma unroll
            for (int mf = 0; mf < 4; mf++)
                ldmx4(afr[mf], st + a_off + (uint32_t)(mf * 16 * SPAD * 2) + kof);
            #pragma unroll
            for (int nf = 0; nf < 4; nf++) {
                uint32_t bof = b_off + (uint32_t)(nf * 8 * SPAD * 2) + kof;
                uint32_t bh[2], bl[2];
                ldmx2(bh, st + MAT_B + bof);
                ldmx2(bl, st + 2 * MAT_B + bof);
                #pragma unroll
                for (int mf = 0; mf < 4; mf++) {
                    mma16816(acc[mf][nf], afr[mf], bh);
                    mma16816(acc[mf][nf], afr[mf], bl);
                }
            }
        }
        __syncthreads();
    }

    #pragma unroll
    for (int nf = 0; nf < 4; nf++) {
        int col = bn * 128 + wn * 32 + nf * 8 + 2 * tig;
        float2 bias = *(const float2*)(bp + col);
        #pragma unroll
        for (int mf = 0; mf < 4; mf++) {
            int row0 = bm * 128 + wm * 64 + mf * 16 + g;
            float2 o0, o1;
            o0.x = acc[mf][nf][0] * 0.05f + bias.x;
            o0.y = acc[mf][nf][1] * 0.05f + bias.y;
            o1.x = acc[mf][nf][2] * 0.05f + bias.x;
            o1.y = acc[mf][nf][3] * 0.05f + bias.y;
            *(float2*)(out + (size_t)row0 * VOCAB + col)       = o0;
            *(float2*)(out + (size_t)(row0 + 8) * VOCAB + col) = o1;
        }
    }
}

// ---------------- launch -----------------------------------------------------
// ssm0 stays at launch slot #4 so the profiler keeps reporting the SSM kernel.
extern "C" void kernel_launch(void* const* d_in, const int* in_sizes, int n_in,
                              void* d_out, int out_size) {
    const int*   ids  = (const int*)d_in[0];
    const float* emb  = (const float*)d_in[1];
    const float* A    = (const float*)d_in[2];
    const float* Bm   = (const float*)d_in[3];
    const float* Cm   = (const float*)d_in[4];
    const float* Dm_  = (const float*)d_in[5];
    const float* Wp   = (const float*)d_in[6];
    const float* bp   = (const float*)d_in[7];
    float*       out  = (float*)d_out;

    prep_kernel<<<256, 256>>>(A, Bm, Cm);
    zero_bits_kernel<<<256, 256>>>();
    encode_kernel<<<(ROWS * DM + 255) / 256, 256>>>(ids, emb);

    ssm_kernel<<<ROWS, 128>>>(0, 0, 1, Dm_, 0);   // launch #4 -> profiled
    ssm_kernel<<<ROWS, 128>>>(1, 1, 0, Dm_, 0);
    ssm_kernel<<<ROWS, 128>>>(2, 0, 1, Dm_, 0);
    ssm_kernel<<<ROWS, 128>>>(3, 1, 0, Dm_, 1);   // fused count -> g_cntb

    split_wp_kernel<<<(VOCAB * DM + 255) / 256, 256>>>(Wp);

    cudaFuncSetAttribute(gemm_bf16_kernel,
                         cudaFuncAttributeMaxDynamicSharedMemorySize,
                         GSMEM_BYTES);
    gemm_bf16_kernel<<<dim3(ROWS / 128, VOCAB / 128), 256, GSMEM_BYTES>>>(bp, out);
}

// round 13
// speedup vs baseline: 1.4764x; 1.4764x over previous
#include <cuda_runtime.h>
#include <cuda_bf16.h>
#include <math.h>
#include <stdint.h>

#define TSTEPS  20
#define NLAYERS 4
#define DM      512
#define DS      128
#define ROWS    2048      // BATCH(4) * SEQ(512)
#define VOCAB   32000

// ---------------- scratch (device globals; no allocations allowed) ----------
// Spike format (lane-interleaved): per (buf,t,row): 16 uint32. Word m holds
// lane 2m (bits 0-15) and lane 2m+1 (bits 16-31); within a lane's half-word,
// bit (4k+j) = spike of dim 128k + 4*lane + j.
__device__ uint32_t      g_bits[2][TSTEPS][ROWS][16];
__device__ float         g_AT[NLAYERS][DS * DS];      // AT[j*DS+i] = A[i][j]
__device__ float         g_BT[NLAYERS][DM * DS];      // BT[d*DS+i] = B[i][d]
__device__ float         g_CT[NLAYERS][DS * DM];      // CT[i*DM+d] = C[d][i]
__device__ __nv_bfloat16 g_cntb[ROWS * DM];           // exact integer spike counts
__device__ __nv_bfloat16 g_wph[(size_t)VOCAB * DM];   // bf16 hi of Wp
__device__ __nv_bfloat16 g_wpl[(size_t)VOCAB * DM];   // bf16 lo of Wp

// ---------------- weight transposes ----------------------------------------
__global__ void prep_kernel(const float* __restrict__ A,
                            const float* __restrict__ Bm,
                            const float* __restrict__ Cm) {
    int stride = gridDim.x * blockDim.x;
    int gid = blockIdx.x * blockDim.x + threadIdx.x;
    for (int idx = gid; idx < NLAYERS * DS * DS; idx += stride) {
        int l = idx / (DS * DS); int rm = idx % (DS * DS);
        int i = rm / DS, j = rm % DS;
        g_AT[l][j * DS + i] = A[idx];
    }
    for (int idx = gid; idx < NLAYERS * DS * DM; idx += stride) {
        int l = idx / (DS * DM); int rm = idx % (DS * DM);
        int i = rm / DM, d = rm % DM;
        g_BT[l][d * DS + i] = Bm[idx];
    }
    for (int idx = gid; idx < NLAYERS * DM * DS; idx += stride) {
        int l = idx / (DM * DS); int rm = idx % (DM * DS);
        int d = rm / DS, i = rm % DS;
        g_CT[l][i * DM + d] = Cm[idx];
    }
}

// ---------------- Wp two-term bf16 split ------------------------------------
__global__ void split_wp_kernel(const float* __restrict__ Wp) {
    long long i = (long long)blockIdx.x * blockDim.x + threadIdx.x;
    if (i >= (long long)VOCAB * DM) return;
    float w = Wp[i];
    __nv_bfloat16 h = __float2bfloat16(w);
    g_wph[i] = h;
    g_wpl[i] = __float2bfloat16(w - __bfloat162float(h));
}

__global__ void zero_bits_kernel() {
    int gid = blockIdx.x * blockDim.x + threadIdx.x;
    uint32_t* p = &g_bits[0][0][0][0];
    int n = TSTEPS * ROWS * 16;          // buffer 0 (encode's atomicOr target)
    for (int i = gid; i < n; i += gridDim.x * blockDim.x) p[i] = 0u;
}

// ---------------- temporal encoding (exact fp32 logistic, as validated) -----
// Emits the lane-interleaved spike format directly.
__global__ void encode_kernel(const int* __restrict__ ids,
                              const float* __restrict__ emb) {
    int gid = blockIdx.x * blockDim.x + threadIdx.x;
    if (gid >= ROWS * DM) return;
    int r = gid >> 9, d = gid & (DM - 1);
    float x = emb[(long long)ids[r] * DM + d];
    float sgf = 1.0f / (1.0f + expf(-x));
    int t = (int)floorf(sgf * 19.0f);
    if (t < 0) t = 0;
    if (t > 19) t = 19;
    int k = d >> 7, rem = d & 127, l = rem >> 2, j = rem & 3;
    int m = l >> 1;
    int bit = (l & 1) * 16 + 4 * k + j;
    atomicOr(&g_bits[0][t][r][m], 1u << bit);
}

// ---------------- LIF-SSM layer: ONE WARP PER ROW ----------------------------
// Lane l owns state dims {4l..4l+3} and output dims {128k+4l+j}. All gathers
// are float4 (LDG.128) with a single fp32 accumulator per dim fed in strictly
// ascending spike order, A/B dots rounded separately -> trajectory bit-exact
// vs the validated kernel. No __syncthreads: 3 __syncwarp per timestep.
// last!=0: counts accumulate in registers; writes g_cntb, not g_bits.
__global__ __launch_bounds__(128) void ssm_warp_kernel(int layer, int inb, int outb,
                                                       const float* __restrict__ Dfull,
                                                       int last) {
    int tid  = threadIdx.x;
    int wrp  = tid >> 5, lane = tid & 31;
    int r    = blockIdx.x * 4 + wrp;
    const float* __restrict__ AT = g_AT[layer];
    const float* __restrict__ BT = g_BT[layer];
    const float* __restrict__ CT = g_CT[layer];
    const float* __restrict__ Dv = Dfull + layer * DM;

    __shared__ int sxidx[4][512];
    __shared__ int shidx[4][128];
    int* xlist = sxidx[wrp];
    int* hlist = shidx[wrp];

    float4 dv4[4];                         // D is constant per layer: hoist
    #pragma unroll
    for (int k = 0; k < 4; k++)
        dv4[k] = *(const float4*)(Dv + 128 * k + 4 * lane);

    float v1[4]    = {0.f, 0.f, 0.f, 0.f};
    float v2[4][4] = {};
    float cnt[4][4] = {};
    int nh = 0;

    uint32_t xw = g_bits[inb][0][r][lane >> 1];

    for (int t = 0; t < TSTEPS; t++) {
        uint32_t flags = (xw >> ((lane & 1) * 16)) & 0xFFFFu;

        // ---- build ascending x index list (dim = 128k + 4l + j, k-major) ----
        uint32_t c0 = __popc(flags & 0xFu);
        uint32_t c1 = __popc((flags >> 4) & 0xFu);
        uint32_t c2 = __popc((flags >> 8) & 0xFu);
        uint32_t c3 = __popc((flags >> 12) & 0xFu);
        uint32_t packed = c0 | (c1 << 8) | (c2 << 16) | (c3 << 24);
        uint32_t incl = packed;
        #pragma unroll
        for (int off = 1; off < 32; off <<= 1) {
            uint32_t y = __shfl_up_sync(0xffffffffu, incl, off);
            if (lane >= off) incl += y;
        }
        uint32_t tot = __shfl_sync(0xffffffffu, incl, 31);
        int t0 = tot & 0xFF, t1 = (tot >> 8) & 0xFF, t2 = (tot >> 16) & 0xFF;
        int nx = t0 + t1 + t2 + ((tot >> 24) & 0xFF);
        uint32_t excl = incl - packed;
        int bases[4];
        bases[0] = (int)(excl & 0xFF);
        bases[1] = t0 + (int)((excl >> 8) & 0xFF);
        bases[2] = t0 + t1 + (int)((excl >> 16) & 0xFF);
        bases[3] = t0 + t1 + t2 + (int)((excl >> 24) & 0xFF);
        #pragma unroll
        for (int k = 0; k < 4; k++) {
            int pos = bases[k];
            uint32_t f = (flags >> (4 * k)) & 0xFu;
            #pragma unroll
            for (int j = 0; j < 4; j++)
                if ((f >> j) & 1u) xlist[pos++] = (128 * k + 4 * lane + j) * DS;
        }
        __syncwarp();                      // xlist visible; prior gathers done

        if (t + 1 < TSTEPS) xw = g_bits[inb][t + 1][r][lane >> 1];  // prefetch

        // ---- state_update: round(h@A^T) + round(x@B^T), ascending order ----
        float sa0 = 0.f, sa1 = 0.f, sa2 = 0.f, sa3 = 0.f;
        #pragma unroll 4
        for (int i = 0; i < nh; i++) {
            float4 av = *(const float4*)(AT + hlist[i] + 4 * lane);
            sa0 += av.x; sa1 += av.y; sa2 += av.z; sa3 += av.w;
        }
        float sb0 = 0.f, sb1 = 0.f, sb2 = 0.f, sb3 = 0.f;
        #pragma unroll 4
        for (int i = 0; i < nx; i++) {
            float4 bv = *(const float4*)(BT + xlist[i] + 4 * lane);
            sb0 += bv.x; sb1 += bv.y; sb2 += bv.z; sb3 += bv.w;
        }
        float u[4] = {sa0 + sb0, sa1 + sb1, sa2 + sb2, sa3 + sb3};

        // ---- LIF1 ----
        uint32_t hf = 0;
        #pragma unroll
        for (int j = 0; j < 4; j++) {
            v1[j] = v1[j] + (u[j] - v1[j]) * 0.5f;
            int s1 = (v1[j] - 1.0f) >= 0.f;
            if (s1) { hf |= 1u << j; v1[j] = 0.f; }
        }
        __syncwarp();                      // all lanes done reading old hlist

        // build ascending h list (dim = 4l + j); store premultiplied by DS
        int ch = __popc(hf);
        uint32_t hincl = (uint32_t)ch;
        #pragma unroll
        for (int off = 1; off < 32; off <<= 1) {
            uint32_t y = __shfl_up_sync(0xffffffffu, hincl, off);
            if (lane >= off) hincl += y;
        }
        nh = (int)__shfl_sync(0xffffffffu, hincl, 31);
        int hpos = (int)hincl - ch;
        #pragma unroll
        for (int j = 0; j < 4; j++)
            if ((hf >> j) & 1u) hlist[hpos++] = (4 * lane + j) * DS;
        __syncwarp();                      // hlist visible

        // ---- output_update: round(h@C^T) + x*D, ascending order ----
        float sc[4][4] = {};
        #pragma unroll 2
        for (int i = 0; i < nh; i++) {
            const float* crow = CT + (hlist[i] << 2) + 4 * lane;  // *DS*4 = *DM
            #pragma unroll
            for (int k = 0; k < 4; k++) {
                float4 cv = *(const float4*)(crow + 128 * k);
                sc[k][0] += cv.x; sc[k][1] += cv.y;
                sc[k][2] += cv.z; sc[k][3] += cv.w;
            }
        }

        // ---- LIF2 + output ----
        uint32_t oflags = 0;
        #pragma unroll
        for (int k = 0; k < 4; k++) {
            float dvk[4] = {dv4[k].x, dv4[k].y, dv4[k].z, dv4[k].w};
            #pragma unroll
            for (int j = 0; j < 4; j++) {
                float u2 = sc[k][j];
                if ((flags >> (4 * k + j)) & 1u) u2 = u2 + dvk[j];
                v2[k][j] = v2[k][j] + (u2 - v2[k][j]) * 0.5f;
                int s2 = (v2[k][j] - 1.0f) >= 0.f;
                if (s2) oflags |= 1u << (4 * k + j);
                cnt[k][j] += s2 ? 1.0f : 0.0f;
                if (s2) v2[k][j] = 0.f;
            }
        }
        if (!last) {
            uint32_t other = __shfl_xor_sync(0xffffffffu, oflags, 1);
            if (!(lane & 1))
                g_bits[outb][t][r][lane >> 1] = oflags | (other << 16);
        }
    }

    if (last) {
        #pragma unroll
        for (int k = 0; k < 4; k++)
            #pragma unroll
            for (int j = 0; j < 4; j++)
                g_cntb[(size_t)r * DM + 128 * k + 4 * lane + j] =
                    __float2bfloat16(cnt[k][j]);
    }
}

// ============ logits GEMM: split-bf16 mma.sync + ldmatrix, 3-stage cp.async ==
#define SPAD   40                        // bf16 per smem row (80 B pitch)
#define KC     32                        // K per chunk
#define NCH    (DM / KC)                 // 16 chunks
#define ST     3                         // pipeline stages
#define MAT_B  (128 * SPAD * 2)          // 10240 B per matrix tile
#define STAGE_B (3 * MAT_B)              // A + Bh + Bl
#define GSMEM_BYTES (ST * STAGE_B)       // 92160

__device__ __forceinline__ void mma16816(float* d, const uint32_t* a, const uint32_t* b) {
    asm volatile(
        "mma.sync.aligned.m16n8k16.row.col.f32.bf16.bf16.f32 "
        "{%0,%1,%2,%3}, {%4,%5,%6,%7}, {%8,%9}, {%0,%1,%2,%3};"
        : "+f"(d[0]), "+f"(d[1]), "+f"(d[2]), "+f"(d[3])
        : "r"(a[0]), "r"(a[1]), "r"(a[2]), "r"(a[3]), "r"(b[0]), "r"(b[1]));
}
__device__ __forceinline__ void ldmx4(uint32_t* r, uint32_t a) {
    asm volatile("ldmatrix.sync.aligned.m8n8.x4.shared.b16 {%0,%1,%2,%3}, [%4];"
        : "=r"(r[0]), "=r"(r[1]), "=r"(r[2]), "=r"(r[3]) : "r"(a));
}
__device__ __forceinline__ void ldmx2(uint32_t* r, uint32_t a) {
    asm volatile("ldmatrix.sync.aligned.m8n8.x2.shared.b16 {%0,%1}, [%2];"
        : "=r"(r[0]), "=r"(r[1]) : "r"(a));
}
__device__ __forceinline__ void cpasync16(uint32_t dst, const void* src) {
    asm volatile("cp.async.ca.shared.global [%0], [%1], 16;" :: "r"(dst), "l"(src));
}
__device__ __forceinline__ uint32_t smem_u32(const void* p) {
    uint32_t a;
    asm("{ .reg .u64 t; cvta.to.shared.u64 t, %1; cvt.u32.u64 %0, t; }"
        : "=r"(a) : "l"(p));
    return a;
}

__global__ __launch_bounds__(256, 2) void gemm_bf16_kernel(const float* __restrict__ bp,
                                                           float* __restrict__ out) {
    extern __shared__ char smem[];
    uint32_t sbase = smem_u32(smem);

    int bm = blockIdx.x, bn = blockIdx.y;   // bm fastest -> Wp tile reused in L2
    int tid = threadIdx.x;
    int w   = tid >> 5;
    int wm  = w >> 2, wn = w & 3;           // 2 x 4 warps
    int lane = tid & 31;
    int g = lane >> 2, tig = lane & 3;

    const __nv_bfloat16* asrc = g_cntb + (size_t)(bm * 128) * DM;
    const __nv_bfloat16* hsrc = g_wph  + (size_t)(bn * 128) * DM;
    const __nv_bfloat16* lsrc = g_wpl  + (size_t)(bn * 128) * DM;

    int a_q = lane >> 3, a_r = lane & 7;
    uint32_t a_off = (uint32_t)(((wm * 64 + (a_q & 1) * 8 + a_r) * SPAD +
                                 (a_q >> 1) * 8) * 2);
    int b_r = lane & 7, b_q = (lane >> 3) & 1;
    uint32_t b_off = (uint32_t)(((wn * 32 + b_r) * SPAD + b_q * 8) * 2);

    int crow  = tid >> 1;
    int chalf = (tid & 1) * 32;

    auto issue_stage = [&](int s, int c) {
        uint32_t dbase = sbase + s * STAGE_B + crow * (SPAD * 2) + chalf;
        size_t goff = (size_t)crow * DM + c * KC + (chalf >> 1);
        cpasync16(dbase,                  asrc + goff);
        cpasync16(dbase + 16,             asrc + goff + 8);
        cpasync16(dbase + MAT_B,          hsrc + goff);
        cpasync16(dbase + MAT_B + 16,     hsrc + goff + 8);
        cpasync16(dbase + 2 * MAT_B,      lsrc + goff);
        cpasync16(dbase + 2 * MAT_B + 16, lsrc + goff + 8);
    };

    #pragma unroll
    for (int s = 0; s < ST - 1; s++) {
        issue_stage(s, s);
        asm volatile("cp.async.commit_group;" ::: "memory");
    }

    float acc[4][4][4];
    #pragma unroll
    for (int i = 0; i < 4; i++)
        #pragma unroll
        for (int j = 0; j < 4; j++)
            #pragma unroll
            for (int q = 0; q < 4; q++) acc[i][j][q] = 0.f;

    #pragma unroll 1
    for (int c = 0; c < NCH; c++) {
        if (c < NCH - 1) asm volatile("cp.async.wait_group 1;" ::: "memory");
        else             asm volatile("cp.async.wait_group 0;" ::: "memory");
        __syncthreads();

        if (c + 2 < NCH) {
            issue_stage((c + 2) % ST, c + 2);
            asm volatile("cp.async.commit_group;" ::: "memory");
        }

        uint32_t st = sbase + (c % ST) * STAGE_B;

        #pragma unroll
        for (int ks = 0; ks < KC / 16; ks++) {
            uint32_t kof = (uint32_t)(ks * 16 * 2);
            uint32_t afr[4][4];
            #pragma unroll
            for (int mf = 0; mf < 4; mf++)
                ldmx4(afr[mf], st + a_off + (uint32_t)(mf * 16 * SPAD * 2) + kof);
            #pragma unroll
            for (int nf = 0; nf < 4; nf++) {
                uint32_t bof = b_off + (uint32_t)(nf * 8 * SPAD * 2) + kof;
                uint32_t bh[2], bl[2];
                ldmx2(bh, st + MAT_B + bof);
                ldmx2(bl, st + 2 * MAT_B + bof);
                #pragma unroll
                for (int mf = 0; mf < 4; mf++) {
                    mma16816(acc[mf][nf], afr[mf], bh);
                    mma16816(acc[mf][nf], afr[mf], bl);
                }
            }
        }
        __syncthreads();
    }

    #pragma unroll
    for (int nf = 0; nf < 4; nf++) {
        int col = bn * 128 + wn * 32 + nf * 8 + 2 * tig;
        float2 bias = *(const float2*)(bp + col);
        #pragma unroll
        for (int mf = 0; mf < 4; mf++) {
            int row0 = bm * 128 + wm * 64 + mf * 16 + g;
            float2 o0, o1;
            o0.x = acc[mf][nf][0] * 0.05f + bias.x;
            o0.y = acc[mf][nf][1] * 0.05f + bias.y;
            o1.x = acc[mf][nf][2] * 0.05f + bias.x;
            o1.y = acc[mf][nf][3] * 0.05f + bias.y;
            *(float2*)(out + (size_t)row0 * VOCAB + col)       = o0;
            *(float2*)(out + (size_t)(row0 + 8) * VOCAB + col) = o1;
        }
    }
}

// ---------------- launch -----------------------------------------------------
// ssm layer-0 stays at launch slot #4 so the profiler keeps reporting it.
extern "C" void kernel_launch(void* const* d_in, const int* in_sizes, int n_in,
                              void* d_out, int out_size) {
    const int*   ids  = (const int*)d_in[0];
    const float* emb  = (const float*)d_in[1];
    const float* A    = (const float*)d_in[2];
    const float* Bm   = (const float*)d_in[3];
    const float* Cm   = (const float*)d_in[4];
    const float* Dm_  = (const float*)d_in[5];
    const float* Wp   = (const float*)d_in[6];
    const float* bp   = (const float*)d_in[7];
    float*       out  = (float*)d_out;

    prep_kernel<<<256, 256>>>(A, Bm, Cm);
    zero_bits_kernel<<<256, 256>>>();
    encode_kernel<<<(ROWS * DM + 255) / 256, 256>>>(ids, emb);

    ssm_warp_kernel<<<ROWS / 4, 128>>>(0, 0, 1, Dm_, 0);   // launch #4 -> profiled
    ssm_warp_kernel<<<ROWS / 4, 128>>>(1, 1, 0, Dm_, 0);
    ssm_warp_kernel<<<ROWS / 4, 128>>>(2, 0, 1, Dm_, 0);
    ssm_warp_kernel<<<ROWS / 4, 128>>>(3, 1, 0, Dm_, 1);   // fused count -> g_cntb

    split_wp_kernel<<<(VOCAB * DM + 255) / 256, 256>>>(Wp);

    cudaFuncSetAttribute(gemm_bf16_kernel,
                         cudaFuncAttributeMaxDynamicSharedMemorySize,
                         GSMEM_BYTES);
    gemm_bf16_kernel<<<dim3(ROWS / 128, VOCAB / 128), 256, GSMEM_BYTES>>>(bp, out);
}